// round 3
// baseline (speedup 1.0000x reference)
#include <cuda_runtime.h>
#include <cstddef>

// Monarch embedding, analytically folded:
//   out[tok][kr*32+o] = (kr&1 == s) ? L[v*16 + kr/2] * R[(kr*32 + c)*32 + o] : 0
//   v = x[tok], k = v/786, s = k>>5, c = k&31.
//
// 64 MiB output is L2-resident -> latency-bound, not HBM-bound.
// 8 tokens/CTA for MLP=8 per thread. 8 warps, parity-pure:
// warps 0-3 parity 0, warps 4-7 parity 1. Each thread: one (kr, o) slot.
// Zero-parity tokens cost a warp just one predicated-off load pair + STG.

__global__ void __launch_bounds__(256) monarch_embed_kernel(
    const int* __restrict__ x,
    const float* __restrict__ L,
    const float* __restrict__ R,
    float* __restrict__ out)
{
    constexpr int T = 8;                   // tokens per CTA
    const int tb  = blockIdx.x * T;
    const int tid = threadIdx.x;
    const int w   = tid >> 5;
    const int l   = tid & 31;
    const int p   = w >> 2;                // warp parity (0/1)
    const int q   = w & 3;
    const int r   = l >> 3;
    const int o   = (l & 7) << 2;
    const int i   = (q << 2) + r;          // 0..15
    const int kr  = (i << 1) + p;          // 0..31

    // Two aligned 128-bit loads cover x for all 8 tokens.
    const int4 xa = *reinterpret_cast<const int4*>(x + tb);
    const int4 xb = *reinterpret_cast<const int4*>(x + tb + 4);
    const int vs[T] = {xa.x, xa.y, xa.z, xa.w, xb.x, xb.y, xb.z, xb.w};

    float  lv[T];
    float4 r4[T];
    bool   act[T];

    // Phase 1: issue all gathers (independent chains; ptxas predicates them).
#pragma unroll
    for (int t = 0; t < T; t++) {
        const int v = vs[t];
        const int k = v / 786;
        const int s = k >> 5;
        const int c = k & 31;
        act[t] = (s == p);                 // warp-uniform
        if (act[t]) {
            lv[t] = __ldg(&L[(size_t)v * 16 + i]);
            r4[t] = *reinterpret_cast<const float4*>(
                &R[((size_t)((kr << 5) + c) << 5) + o]);
        }
    }

    // Phase 2: multiply + store.
    float* ob = out + (size_t)tb * 1024 + (kr << 5) + o;
#pragma unroll
    for (int t = 0; t < T; t++) {
        float4 res = make_float4(0.f, 0.f, 0.f, 0.f);
        if (act[t]) {
            res = make_float4(lv[t] * r4[t].x, lv[t] * r4[t].y,
                              lv[t] * r4[t].z, lv[t] * r4[t].w);
        }
        *reinterpret_cast<float4*>(ob + (size_t)t * 1024) = res;
    }
}

extern "C" void kernel_launch(void* const* d_in, const int* in_sizes, int n_in,
                              void* d_out, int out_size) {
    const int*   x = (const int*)  d_in[0];   // (8, 2048) int32
    const float* L = (const float*)d_in[1];   // (64, 786, 16) f32
    const float* R = (const float*)d_in[2];   // (32, 32, 32) f32
    // d_in[3] = p : analytically folded (perfect_shuffle(64, 1024))

    const int ntok = out_size / 1024;         // 16384 tokens
    monarch_embed_kernel<<<ntok / 8, 256>>>(x, L, R, (float*)d_out);
}

// round 4
// speedup vs baseline: 1.4258x; 1.4258x over previous
#include <cuda_runtime.h>
#include <cstddef>

// Monarch embedding, analytically folded:
//   out[tok][kr*32+o] = (kr&1 == s) ? L[v*16 + kr/2] * R[(kr*32 + c)*32 + o] : 0
//   v = x[tok], k = v/786, s = k>>5, c = k&31.
//
// 64 MiB output is L2-resident -> latency bound. 8 tokens/CTA.
// MLP=8 ONLY on the long-latency L gathers (8 scalar regs).
// R loads are L1-hot (~39cyc) -> loaded inside the store loop (1-iter live
// range). No branches: both loads are always in-bounds; parity mask applied
// as a SEL on the L scalar (lv=0 -> row of zeros).
// Warps parity-pure: warp w -> p=w>>2, rows kr = 2*(4*(w&3)+l/8) + p.

__global__ void __launch_bounds__(256, 6) monarch_embed_kernel(
    const int* __restrict__ x,
    const float* __restrict__ L,
    const float* __restrict__ R,
    float* __restrict__ out)
{
    constexpr int T = 8;                   // tokens per CTA
    const int tb  = blockIdx.x * T;
    const int tid = threadIdx.x;
    const int w   = tid >> 5;
    const int l   = tid & 31;
    const int p   = w >> 2;                // warp parity (0/1)
    const int q   = w & 3;
    const int r   = l >> 3;
    const int o   = (l & 7) << 2;
    const int i   = (q << 2) + r;          // 0..15
    const int kr  = (i << 1) + p;          // 0..31

    // Two aligned 128-bit loads cover x for all 8 tokens.
    const int4 xa = *reinterpret_cast<const int4*>(x + tb);
    const int4 xb = *reinterpret_cast<const int4*>(x + tb + 4);
    const int vs[T] = {xa.x, xa.y, xa.z, xa.w, xb.x, xb.y, xb.z, xb.w};

    // Phase 1: fire all 8 long-latency L gathers (unconditional, in-bounds).
    float lv[T];
#pragma unroll
    for (int t = 0; t < T; t++)
        lv[t] = __ldg(&L[(size_t)vs[t] * 16 + i]);

    // Phase 2: per token -> L1-hot R load, parity select, mul, store.
    float* ob = out + (size_t)tb * 1024 + (kr << 5) + o;
#pragma unroll
    for (int t = 0; t < T; t++) {
        const int k = vs[t] / 786;
        const int s = k >> 5;
        const int c = k & 31;
        const float4 r4 = *reinterpret_cast<const float4*>(
            &R[((size_t)((kr << 5) + c) << 5) + o]);
        const float lvv = (s == p) ? lv[t] : 0.0f;   // one SEL, no branch
        const float4 res = make_float4(lvv * r4.x, lvv * r4.y,
                                       lvv * r4.z, lvv * r4.w);
        *reinterpret_cast<float4*>(ob + (size_t)t * 1024) = res;
    }
}

extern "C" void kernel_launch(void* const* d_in, const int* in_sizes, int n_in,
                              void* d_out, int out_size) {
    const int*   x = (const int*)  d_in[0];   // (8, 2048) int32
    const float* L = (const float*)d_in[1];   // (64, 786, 16) f32
    const float* R = (const float*)d_in[2];   // (32, 32, 32) f32
    // d_in[3] = p : analytically folded (perfect_shuffle(64, 1024))

    const int ntok = out_size / 1024;         // 16384 tokens
    monarch_embed_kernel<<<ntok / 8, 256>>>(x, L, R, (float*)d_out);
}

// round 5
// speedup vs baseline: 1.4989x; 1.0512x over previous
#include <cuda_runtime.h>
#include <cstddef>

// Monarch embedding, analytically folded:
//   out[tok][kr*32+o] = (kr&1 == s) ? L[v*16 + kr/2] * R[(kr*32 + c)*32 + o] : 0
//   v = x[tok], k = v/786, s = k>>5, c = k&31.
//
// 64 MiB output is L2-resident -> latency bound; currency = resident warps.
// T=4 tokens/CTA keeps payload regs at 8 (vs[4] + lv[4]) -> ~30 regs total
// -> 8 CTAs/SM (100% theoretical occupancy). Phase-split: all long-latency
// L gathers fired up front (plus the x int4) for MLP=5 front-batched loads;
// R loads are L1-hot and live one iteration. Branch-free: parity applied as
// SEL on the L scalar.
// Warps parity-pure: warp w -> p=w>>2, rows kr = 2*(4*(w&3)+l/8) + p.

#define TOKENS_PER_CTA 4

__global__ void __launch_bounds__(256) monarch_embed_kernel(
    const int* __restrict__ x,
    const float* __restrict__ L,
    const float* __restrict__ R,
    float* __restrict__ out)
{
    constexpr int T = TOKENS_PER_CTA;
    const int tb  = blockIdx.x * T;
    const int tid = threadIdx.x;
    const int w   = tid >> 5;
    const int l   = tid & 31;
    const int p   = w >> 2;                // warp parity (0/1)
    const int q   = w & 3;
    const int r   = l >> 3;
    const int o   = (l & 7) << 2;
    const int i   = (q << 2) + r;          // 0..15
    const int kr  = (i << 1) + p;          // 0..31

    // One aligned 128-bit load covers x for all 4 tokens.
    const int4 xv = *reinterpret_cast<const int4*>(x + tb);
    const int vs[T] = {xv.x, xv.y, xv.z, xv.w};

    // Phase 1: fire all long-latency L gathers (unconditional, in-bounds).
    float lv[T];
#pragma unroll
    for (int t = 0; t < T; t++)
        lv[t] = __ldg(&L[(size_t)vs[t] * 16 + i]);

    // Phase 2: per token -> L1-hot R load, parity SEL, mul, store.
    float* ob = out + (size_t)tb * 1024 + (kr << 5) + o;
#pragma unroll
    for (int t = 0; t < T; t++) {
        const int k = vs[t] / 786;         // recomputed: regs > ALU here
        const int s = k >> 5;
        const int c = k & 31;
        const float4 r4 = *reinterpret_cast<const float4*>(
            &R[((size_t)((kr << 5) + c) << 5) + o]);
        const float lvv = (s == p) ? lv[t] : 0.0f;   // one SEL, no branch
        const float4 res = make_float4(lvv * r4.x, lvv * r4.y,
                                       lvv * r4.z, lvv * r4.w);
        *reinterpret_cast<float4*>(ob + (size_t)t * 1024) = res;
    }
}

extern "C" void kernel_launch(void* const* d_in, const int* in_sizes, int n_in,
                              void* d_out, int out_size) {
    const int*   x = (const int*)  d_in[0];   // (8, 2048) int32
    const float* L = (const float*)d_in[1];   // (64, 786, 16) f32
    const float* R = (const float*)d_in[2];   // (32, 32, 32) f32
    // d_in[3] = p : analytically folded (perfect_shuffle(64, 1024))

    const int ntok = out_size / 1024;         // 16384 tokens
    monarch_embed_kernel<<<ntok / TOKENS_PER_CTA, 256>>>(x, L, R, (float*)d_out);
}